// round 17
// baseline (speedup 1.0000x reference)
#include <cuda_runtime.h>

#define NB   32
#define CIN  64
#define COUT 128
#define HW   4096               // 64*64 spatial floats per (n,ci)
#define INV_OHW (1.0f/4489.0f)  // 1/(67*67)

#define ROWS_PER_BLK 4
#define XTHREADS 512
#define NXB  (NB * CIN / ROWS_PER_BLK)   // 512 x-blocks
#define NWB  CIN                          // 64 w-blocks
#define GRID (NXB + NWB)                  // 576 blocks, ~3.9/SM

__device__ float g_Sx[NB * CIN];
__device__ float g_Sw[CIN * COUT];

__device__ __forceinline__ float warp_sum(float v) {
    v += __shfl_xor_sync(0xffffffffu, v, 16);
    v += __shfl_xor_sync(0xffffffffu, v, 8);
    v += __shfl_xor_sync(0xffffffffu, v, 4);
    v += __shfl_xor_sync(0xffffffffu, v, 2);
    v += __shfl_xor_sync(0xffffffffu, v, 1);
    return v;
}
__device__ __forceinline__ float warp_max(float v) {
    v = fmaxf(v, __shfl_xor_sync(0xffffffffu, v, 16));
    v = fmaxf(v, __shfl_xor_sync(0xffffffffu, v, 8));
    v = fmaxf(v, __shfl_xor_sync(0xffffffffu, v, 4));
    v = fmaxf(v, __shfl_xor_sync(0xffffffffu, v, 2));
    v = fmaxf(v, __shfl_xor_sync(0xffffffffu, v, 1));
    return v;
}

// Kernel 1: reduction, 512-thread / 4-row x-blocks (last untested geometry).
// Each thread: 8 front-batched LDG.128; each 128-thread group owns one row.
__global__ void __launch_bounds__(XTHREADS) reduce_kernel(
    const float* __restrict__ x,
    const float* __restrict__ w)
{
    const int b = blockIdx.x;
    const int t = threadIdx.x;
    const int lane = t & 31;
    const int wid  = t >> 5;     // 0..15

    if (b < NXB) {
        // Block covers rows [4b, 4b+4). Thread t reads 8 float4 spread over
        // the 16KB-contiguous 4-row region: index t + i*512, i=0..7.
        const float4* p = reinterpret_cast<const float4*>(x)
                        + (size_t)b * (ROWS_PER_BLK * HW / 4);
        // Row owner: each 1024-float4 chunk = one row. Thread t's 8 accesses
        // t+0*512 and t+1*512 fall in row (t>>?)... use per-row layout instead:
        // group g = t/128 owns row 4b+g; within group, 128 threads × 8 loads
        // cover the row's 1024 float4.
        const int g  = t >> 7;          // 0..3  (row within block)
        const int tt = t & 127;         // 0..127
        const float4* q = p + (size_t)g * (HW / 4);

        float4 v0 = q[tt];
        float4 v1 = q[tt + 128];
        float4 v2 = q[tt + 256];
        float4 v3 = q[tt + 384];
        float4 v4 = q[tt + 512];
        float4 v5 = q[tt + 640];
        float4 v6 = q[tt + 768];
        float4 v7 = q[tt + 896];

        float s = ((v0.x + v0.y) + (v0.z + v0.w))
                + ((v1.x + v1.y) + (v1.z + v1.w))
                + ((v2.x + v2.y) + (v2.z + v2.w))
                + ((v3.x + v3.y) + (v3.z + v3.w))
                + ((v4.x + v4.y) + (v4.z + v4.w))
                + ((v5.x + v5.y) + (v5.z + v5.w))
                + ((v6.x + v6.y) + (v6.z + v6.w))
                + ((v7.x + v7.y) + (v7.z + v7.w));
        s = warp_sum(s);

        __shared__ float sh[16];
        if (lane == 0) sh[wid] = s;
        __syncthreads();
        // warp w of group g: wids 4g..4g+3. Thread tt==0 of each group sums.
        if (tt == 0) {
            float u = ((sh[4 * g + 0] + sh[4 * g + 1])
                     + (sh[4 * g + 2] + sh[4 * g + 3]));
            g_Sx[b * ROWS_PER_BLK + g] = u;
        }
    } else {
        // w-block: one per ci, thread co sums its 16 contiguous taps
        const int ci = b - NXB;
        if (t < COUT) {
            const float4* p = reinterpret_cast<const float4*>(w)
                            + ((size_t)ci * COUT + t) * 4;
            float4 a0 = p[0], a1 = p[1], a2 = p[2], a3 = p[3];
            g_Sw[ci * COUT + t] =
                ((a0.x + a0.y) + (a0.z + a0.w)) +
                ((a1.x + a1.y) + (a1.z + a1.w)) +
                ((a2.x + a2.y) + (a2.z + a2.w)) +
                ((a3.x + a3.y) + (a3.z + a3.w));
        }
    }
}

// Kernel 2: one block per n, 128 threads (one per co). Proven shape.
__global__ void __launch_bounds__(COUT) finalize_kernel(
    const float* __restrict__ cb,
    const float* __restrict__ eb,
    float* __restrict__ out)
{
    const int n  = blockIdx.x;
    const int co = threadIdx.x;
    const int lane = co & 31;
    const int wid  = co >> 5;

    __shared__ float sx[CIN];
    if (co < CIN) sx[co] = g_Sx[n * CIN + co];
    __syncthreads();

    float a0 = 0.f, a1 = 0.f, a2 = 0.f, a3 = 0.f;
    #pragma unroll
    for (int ci = 0; ci < CIN; ci += 4) {
        a0 = fmaf(sx[ci + 0], g_Sw[(ci + 0) * COUT + co], a0);
        a1 = fmaf(sx[ci + 1], g_Sw[(ci + 1) * COUT + co], a1);
        a2 = fmaf(sx[ci + 2], g_Sw[(ci + 2) * COUT + co], a2);
        a3 = fmaf(sx[ci + 3], g_Sw[(ci + 3) * COUT + co], a3);
    }
    const float pooled = ((a0 + a1) + (a2 + a3)) * INV_OHW + cb[co] + eb[co];

    __shared__ float red[4], red2[4];
    float m = warp_max(pooled);
    if (lane == 0) red[wid] = m;
    __syncthreads();
    const float m0 = fmaxf(fmaxf(red[0], red[1]), fmaxf(red[2], red[3]));

    float e = warp_sum(__expf(pooled - m0));
    if (lane == 0) red2[wid] = e;
    __syncthreads();
    if (co == 0) {
        float tot = (red2[0] + red2[1]) + (red2[2] + red2[3]);
        out[n] = 10.0f * (m0 + logf(tot));
    }
}

extern "C" void kernel_launch(void* const* d_in, const int* in_sizes, int n_in,
                              void* d_out, int out_size) {
    const float* x  = (const float*)d_in[0];   // (32,64,64,64)
    const float* w  = (const float*)d_in[1];   // (64,128,4,4)
    const float* cb = (const float*)d_in[2];   // (128,)
    const float* eb = (const float*)d_in[3];   // (128,)
    float* out = (float*)d_out;                // (32,1)

    reduce_kernel<<<GRID, XTHREADS>>>(x, w);
    finalize_kernel<<<NB, COUT>>>(cb, eb, out);
}